// round 1
// baseline (speedup 1.0000x reference)
#include <cuda_runtime.h>
#include <cstdint>

#define NF     2560
#define TW     16
#define HWDIM  9216
#define BT     1920   // B*T
#define T_LEN  240
#define BATCH  8

// Scratch for intermediate g_sin / g_cos, layout [m = b*T + t][f]
__device__ float g_buf0[BT * NF];
__device__ float g_buf1[BT * NF];

__device__ __forceinline__ unsigned smem_u32(const void* p) {
    return (unsigned)__cvta_generic_to_shared(p);
}

__device__ __forceinline__ void cp_async16(unsigned saddr, const void* gaddr) {
    asm volatile("cp.async.cg.shared.global [%0], [%1], 16;\n" :: "r"(saddr), "l"(gaddr));
}

__device__ __forceinline__ unsigned tf32_of(float f) {
    unsigned r;
    asm("cvt.rna.tf32.f32 %0, %1;" : "=r"(r) : "f"(f));
    return r;
}

__device__ __forceinline__ void mma_tf32(float* c, const unsigned* a, const unsigned* b) {
    asm volatile(
        "mma.sync.aligned.m16n8k8.row.col.f32.tf32.tf32.f32 "
        "{%0,%1,%2,%3}, {%4,%5,%6,%7}, {%8,%9}, {%0,%1,%2,%3};\n"
        : "+f"(c[0]), "+f"(c[1]), "+f"(c[2]), "+f"(c[3])
        : "r"(a[0]), "r"(a[1]), "r"(a[2]), "r"(a[3]), "r"(b[0]), "r"(b[1]));
}

// ---------------------------------------------------------------------------
// Kernel 1: spatial contraction (GEMM).  G[m, f] = sum_k x[m, k] * w[f, k]
// Block tile 128x128, BK=32, 256 threads (8 warps, warp tile 64x32).
// blockIdx.z: 0 -> w_s_sin -> g_buf0, 1 -> w_s_cos -> g_buf1.
// ---------------------------------------------------------------------------
__global__ void __launch_bounds__(256, 2)
spatial_gemm_kernel(const float* __restrict__ x,
                    const float* __restrict__ w_sin,
                    const float* __restrict__ w_cos) {
    __shared__ float As[128][36];   // pad to 36 floats: conflict-free frag loads
    __shared__ float Bs[128][36];

    const int tid = threadIdx.x;
    const int n0 = blockIdx.x * 128;
    const int m0 = blockIdx.y * 128;
    const float* wmat = blockIdx.z ? w_cos : w_sin;
    float* gout = blockIdx.z ? g_buf1 : g_buf0;

    const int lane = tid & 31;
    const int warp = tid >> 5;
    const int wm = (warp & 1) * 64;   // warp row base within block
    const int wn = (warp >> 1) * 32;  // warp col base within block
    const int gid = lane >> 2;        // 0..7
    const int lid4 = lane & 3;        // 0..3

    float acc[4][4][4];
    #pragma unroll
    for (int i = 0; i < 4; i++)
        #pragma unroll
        for (int j = 0; j < 4; j++)
            #pragma unroll
            for (int k = 0; k < 4; k++) acc[i][j][k] = 0.f;

    // gmem -> smem loader mapping: 1024 float4 per tile, 4 per thread
    const int lrow = tid >> 3;        // 0..31 (+ i*32)
    const int lc = (tid & 7) * 4;     // float col within 32
    const float* ag = x + (size_t)(m0 + lrow) * HWDIM + lc;
    const float* bg = wmat + (size_t)(n0 + lrow) * HWDIM + lc;

    unsigned sa[4], sb[4];
    #pragma unroll
    for (int i = 0; i < 4; i++) {
        sa[i] = smem_u32(&As[lrow + i * 32][lc]);
        sb[i] = smem_u32(&Bs[lrow + i * 32][lc]);
    }

    for (int kt = 0; kt < 288; kt++) {
        const float* a = ag + kt * 32;
        const float* b = bg + kt * 32;
        #pragma unroll
        for (int i = 0; i < 4; i++) {
            cp_async16(sa[i], a + (size_t)i * 32 * HWDIM);
            cp_async16(sb[i], b + (size_t)i * 32 * HWDIM);
        }
        asm volatile("cp.async.commit_group;\n");
        asm volatile("cp.async.wait_group 0;\n");
        __syncthreads();

        #pragma unroll
        for (int kk = 0; kk < 4; kk++) {
            const int k0 = kk * 8 + lid4;
            unsigned af[4][4], bf[4][2];
            #pragma unroll
            for (int mt = 0; mt < 4; mt++) {
                int r = wm + mt * 16 + gid;
                af[mt][0] = tf32_of(As[r][k0]);
                af[mt][1] = tf32_of(As[r + 8][k0]);
                af[mt][2] = tf32_of(As[r][k0 + 4]);
                af[mt][3] = tf32_of(As[r + 8][k0 + 4]);
            }
            #pragma unroll
            for (int nt = 0; nt < 4; nt++) {
                int r = wn + nt * 8 + gid;
                bf[nt][0] = tf32_of(Bs[r][k0]);
                bf[nt][1] = tf32_of(Bs[r][k0 + 4]);
            }
            #pragma unroll
            for (int mt = 0; mt < 4; mt++)
                #pragma unroll
                for (int nt = 0; nt < 4; nt++)
                    mma_tf32(acc[mt][nt], af[mt], bf[nt]);
        }
        __syncthreads();
    }

    // Epilogue: write fp32 accumulators to scratch
    #pragma unroll
    for (int mt = 0; mt < 4; mt++) {
        #pragma unroll
        for (int nt = 0; nt < 4; nt++) {
            int m = m0 + wm + mt * 16 + gid;
            int n = n0 + wn + nt * 8 + lid4 * 2;
            float2 v0 = make_float2(acc[mt][nt][0], acc[mt][nt][1]);
            float2 v1 = make_float2(acc[mt][nt][2], acc[mt][nt][3]);
            *reinterpret_cast<float2*>(&gout[(size_t)m * NF + n]) = v0;
            *reinterpret_cast<float2*>(&gout[(size_t)(m + 8) * NF + n]) = v1;
        }
    }
}

// ---------------------------------------------------------------------------
// Kernel 2: depthwise temporal convs + energy + transpose to (B, T, NF).
// out[b, t, f] = log(sqrt(rs^2 + rc^2) + 1e-5)
//   rs = conv(g_sin, wt_cos) + conv(g_cos, wt_sin)
//   rc = conv(g_cos, wt_cos) - conv(g_sin, wt_sin)
//   conv(g, w)[t] = sum_j g[t - 8 + j] * w[j]   (zeros outside [0, T))
// ---------------------------------------------------------------------------
__global__ void __launch_bounds__(128)
temporal_kernel(const float* __restrict__ wt_sin_g,
                const float* __restrict__ wt_cos_g,
                float* __restrict__ out) {
    const int f = blockIdx.x * 128 + threadIdx.x;
    const int b = blockIdx.y;

    float wts[TW], wtc[TW];
    #pragma unroll
    for (int j = 0; j < TW; j++) {
        wts[j] = wt_sin_g[f * TW + j];
        wtc[j] = wt_cos_g[f * TW + j];
    }

    const float* gs = g_buf0 + (size_t)b * T_LEN * NF + f;
    const float* gc = g_buf1 + (size_t)b * T_LEN * NF + f;

    // sliding window: ws[j] == g[t - 8 + j] for the current t
    float ws[TW], wc[TW];
    #pragma unroll
    for (int j = 0; j < TW; j++) {
        int t = j - 8;
        ws[j] = (t >= 0) ? gs[t * NF] : 0.f;
        wc[j] = (t >= 0) ? gc[t * NF] : 0.f;
    }

    float* op = out + (size_t)b * T_LEN * NF + f;
    for (int t = 0; t < T_LEN; t++) {
        float t1 = 0.f, t2 = 0.f, t3 = 0.f, t4 = 0.f;
        #pragma unroll
        for (int j = 0; j < TW; j++) {
            t1 += ws[j] * wtc[j];
            t2 += wc[j] * wts[j];
            t3 += wc[j] * wtc[j];
            t4 += ws[j] * wts[j];
        }
        float rs = t1 + t2;
        float rc = t3 - t4;
        op[t * NF] = logf(sqrtf(rs * rs + rc * rc) + 1e-5f);

        #pragma unroll
        for (int j = 0; j < TW - 1; j++) { ws[j] = ws[j + 1]; wc[j] = wc[j + 1]; }
        int tn = t + 8;
        ws[TW - 1] = (tn < T_LEN) ? gs[tn * NF] : 0.f;
        wc[TW - 1] = (tn < T_LEN) ? gc[tn * NF] : 0.f;
    }
}

extern "C" void kernel_launch(void* const* d_in, const int* in_sizes, int n_in,
                              void* d_out, int out_size) {
    const float* x       = (const float*)d_in[0];
    const float* w_s_sin = (const float*)d_in[1];
    const float* w_s_cos = (const float*)d_in[2];
    const float* w_t_sin = (const float*)d_in[3];
    const float* w_t_cos = (const float*)d_in[4];
    float* out = (float*)d_out;

    dim3 g1(NF / 128, BT / 128, 2);   // (20, 15, 2)
    spatial_gemm_kernel<<<g1, 256>>>(x, w_s_sin, w_s_cos);

    dim3 g2(NF / 128, BATCH);         // (20, 8)
    temporal_kernel<<<g2, 128>>>(w_t_sin, w_t_cos, out);
}

// round 3
// speedup vs baseline: 1.7126x; 1.7126x over previous
#include <cuda_runtime.h>
#include <cuda_fp16.h>
#include <cstdint>

#define NF      2560
#define TW      16
#define HWDIM   9216
#define BT      1920
#define T_LEN   240
#define BATCH   8

#define BM      128     // bt rows per CTA (M)
#define BNF     128     // filters per CTA (N)
#define KC      64      // halves of K per stage
#define NCHUNK  144     // 9216/64
#define PADROWB 144     // bytes per smem row (64 halves + 8 pad)
#define ARR_BYTES (128 * PADROWB)        // 18432
#define OFF_A   0
#define OFF_BS  ARR_BYTES
#define OFF_BC  (2 * ARR_BYTES)
#define STG_BYTES (3 * ARR_BYTES)        // 55296
#define SMEM_DYN  (3 * STG_BYTES)        // 165888

// fp16 copies of inputs (filled by convert kernel)
__device__ __half x_h[BT * HWDIM];
__device__ __half ws_h[NF * HWDIM];
__device__ __half wc_h[NF * HWDIM];
// intermediate g_sin / g_cos, layout [bt][f]
__device__ float g_buf0[BT * NF];
__device__ float g_buf1[BT * NF];

// ---------------------------------------------------------------------------
__device__ __forceinline__ unsigned smem_u32(const void* p) {
    return (unsigned)__cvta_generic_to_shared(p);
}
__device__ __forceinline__ void cp_async16(unsigned saddr, const void* gaddr) {
    asm volatile("cp.async.cg.shared.global [%0], [%1], 16;\n" :: "r"(saddr), "l"(gaddr));
}
__device__ __forceinline__ void ldsm_x4(uint32_t* r, unsigned addr) {
    asm volatile("ldmatrix.sync.aligned.m8n8.x4.shared.b16 {%0,%1,%2,%3}, [%4];"
                 : "=r"(r[0]), "=r"(r[1]), "=r"(r[2]), "=r"(r[3]) : "r"(addr));
}
__device__ __forceinline__ void mma_fp16(float* c, const uint32_t* a, const uint32_t* b) {
    asm volatile(
        "mma.sync.aligned.m16n8k16.row.col.f32.f16.f16.f32 "
        "{%0,%1,%2,%3}, {%4,%5,%6,%7}, {%8,%9}, {%0,%1,%2,%3};\n"
        : "+f"(c[0]), "+f"(c[1]), "+f"(c[2]), "+f"(c[3])
        : "r"(a[0]), "r"(a[1]), "r"(a[2]), "r"(a[3]), "r"(b[0]), "r"(b[1]));
}

// ---------------------------------------------------------------------------
// Kernel 0: fp32 -> fp16 conversion (vectorized)
// ---------------------------------------------------------------------------
__global__ void __launch_bounds__(256)
f2h_kernel(const float* __restrict__ src, __half* __restrict__ dst, int n4) {
    int i = blockIdx.x * 256 + threadIdx.x;
    if (i < n4) {
        float4 v = reinterpret_cast<const float4*>(src)[i];
        __half2 h0 = __floats2half2_rn(v.x, v.y);
        __half2 h1 = __floats2half2_rn(v.z, v.w);
        reinterpret_cast<__half2*>(dst)[2 * i]     = h0;
        reinterpret_cast<__half2*>(dst)[2 * i + 1] = h1;
    }
}

// ---------------------------------------------------------------------------
// Kernel 1: fused sin+cos spatial GEMM, fp16 mma.sync, 3-stage cp.async.
//   g[m, f] = sum_k x[m,k] * w[f,k]   (A = x row-major, B = w "col" K-major)
// Block tile 128(m) x 128(f), 256 threads, warp tile 64m x 32f, both matrices.
// ---------------------------------------------------------------------------
__global__ void __launch_bounds__(256, 1)
spatial_gemm_fp16(int dummy) {
    extern __shared__ __align__(1024) char smem[];
    const unsigned smem_base = smem_u32(smem);
    const int tid = threadIdx.x;
    const int n0 = blockIdx.x * BNF;   // filter base
    const int m0 = blockIdx.y * BM;    // bt base

    const int lane = tid & 31;
    const int warp = tid >> 5;
    const int wm = (warp & 1) * 64;
    const int wn = (warp >> 1) * 32;

    float acc_s[4][4][4], acc_c[4][4][4];
    #pragma unroll
    for (int i = 0; i < 4; i++)
        #pragma unroll
        for (int j = 0; j < 4; j++)
            #pragma unroll
            for (int k = 0; k < 4; k++) { acc_s[i][j][k] = 0.f; acc_c[i][j][k] = 0.f; }

    // loader mapping: row = tid>>1 (0..127), 4 x 16B segments per thread/array
    const int lrow = tid >> 1;
    const int s0 = (tid & 1) * 4;
    const __half* ga  = x_h  + (size_t)(m0 + lrow) * HWDIM + s0 * 8;
    const __half* gbs = ws_h + (size_t)(n0 + lrow) * HWDIM + s0 * 8;
    const __half* gbc = wc_h + (size_t)(n0 + lrow) * HWDIM + s0 * 8;
    const unsigned lsm = smem_base + lrow * PADROWB + s0 * 16;

    auto load_stage = [&](int kt, int slot) {
        const unsigned sb = lsm + slot * STG_BYTES;
        const __half* pa  = ga  + kt * KC;
        const __half* pbs = gbs + kt * KC;
        const __half* pbc = gbc + kt * KC;
        #pragma unroll
        for (int i = 0; i < 4; i++) {
            cp_async16(sb + OFF_A  + i * 16, pa  + i * 8);
            cp_async16(sb + OFF_BS + i * 16, pbs + i * 8);
            cp_async16(sb + OFF_BC + i * 16, pbc + i * 8);
        }
        asm volatile("cp.async.commit_group;\n");
    };

    // ldmatrix per-lane byte offsets within a stage
    const int mrow = wm + (lane & 7) + 8 * ((lane >> 3) & 1);
    const int akb  = (lane >> 4) * 16;
    unsigned aoff[4];
    #pragma unroll
    for (int mt = 0; mt < 4; mt++) aoff[mt] = (mrow + mt * 16) * PADROWB + akb;

    const int nrow = wn + (lane & 7) + 8 * (lane >> 4);
    const int bkb  = ((lane >> 3) & 1) * 16;
    unsigned boff[2];
    #pragma unroll
    for (int p = 0; p < 2; p++) boff[p] = (nrow + p * 16) * PADROWB + bkb;

    // prologue
    load_stage(0, 0);
    load_stage(1, 1);

    for (int kt = 0; kt < NCHUNK; kt++) {
        if (kt < NCHUNK - 1) asm volatile("cp.async.wait_group 1;\n");
        else                 asm volatile("cp.async.wait_group 0;\n");
        __syncthreads();
        if (kt + 2 < NCHUNK) load_stage(kt + 2, (kt + 2) % 3);

        const unsigned sb = smem_base + (kt % 3) * STG_BYTES;
        #pragma unroll
        for (int kk = 0; kk < 4; kk++) {
            const unsigned kb = kk * 32;
            uint32_t a[4][4], bs[2][4], bc[2][4];
            #pragma unroll
            for (int mt = 0; mt < 4; mt++) ldsm_x4(a[mt], sb + OFF_A + aoff[mt] + kb);
            #pragma unroll
            for (int p = 0; p < 2; p++) {
                ldsm_x4(bs[p], sb + OFF_BS + boff[p] + kb);
                ldsm_x4(bc[p], sb + OFF_BC + boff[p] + kb);
            }
            #pragma unroll
            for (int mt = 0; mt < 4; mt++)
                #pragma unroll
                for (int nt = 0; nt < 4; nt++) {
                    mma_fp16(acc_s[mt][nt], a[mt], &bs[nt >> 1][(nt & 1) * 2]);
                    mma_fp16(acc_c[mt][nt], a[mt], &bc[nt >> 1][(nt & 1) * 2]);
                }
        }
        // next iter's top __syncthreads protects the buffer being overwritten
    }

    // epilogue
    #pragma unroll
    for (int mt = 0; mt < 4; mt++) {
        #pragma unroll
        for (int nt = 0; nt < 4; nt++) {
            int m = m0 + wm + mt * 16 + (lane >> 2);
            int n = n0 + wn + nt * 8 + (lane & 3) * 2;
            *reinterpret_cast<float2*>(&g_buf0[(size_t)m * NF + n]) =
                make_float2(acc_s[mt][nt][0], acc_s[mt][nt][1]);
            *reinterpret_cast<float2*>(&g_buf0[(size_t)(m + 8) * NF + n]) =
                make_float2(acc_s[mt][nt][2], acc_s[mt][nt][3]);
            *reinterpret_cast<float2*>(&g_buf1[(size_t)m * NF + n]) =
                make_float2(acc_c[mt][nt][0], acc_c[mt][nt][1]);
            *reinterpret_cast<float2*>(&g_buf1[(size_t)(m + 8) * NF + n]) =
                make_float2(acc_c[mt][nt][2], acc_c[mt][nt][3]);
        }
    }
}

// ---------------------------------------------------------------------------
// Kernel 2: depthwise temporal convs + energy. Ring-buffer sliding window,
// T split into 5 chunks of 48.
// ---------------------------------------------------------------------------
__global__ void __launch_bounds__(256)
temporal_kernel(const float* __restrict__ wt_sin_g,
                const float* __restrict__ wt_cos_g,
                float* __restrict__ out) {
    const int f = blockIdx.x * 256 + threadIdx.x;
    const int b = blockIdx.y;
    const int t0 = blockIdx.z * 48;

    float wts[TW], wtc[TW];
    #pragma unroll
    for (int j = 0; j < TW; j++) {
        wts[j] = wt_sin_g[f * TW + j];
        wtc[j] = wt_cos_g[f * TW + j];
    }

    const float* gs = g_buf0 + (size_t)b * T_LEN * NF + f;
    const float* gc = g_buf1 + (size_t)b * T_LEN * NF + f;
    float* op = out + (size_t)b * T_LEN * NF + f;

    float rs[TW], rc[TW];
    #pragma unroll
    for (int j = 0; j < TW; j++) {
        int t = t0 - 8 + j;
        int i = t & 15;
        rs[i] = (t >= 0) ? gs[t * NF] : 0.f;
        rc[i] = (t >= 0) ? gc[t * NF] : 0.f;
    }

    #pragma unroll 16
    for (int tt = 0; tt < 48; tt++) {
        const int t = t0 + tt;
        float t1 = 0.f, t2 = 0.f, t3 = 0.f, t4 = 0.f;
        #pragma unroll
        for (int j = 0; j < TW; j++) {
            int i = (tt - 8 + j) & 15;
            t1 += rs[i] * wtc[j];
            t2 += rc[i] * wts[j];
            t3 += rc[i] * wtc[j];
            t4 += rs[i] * wts[j];
        }
        float resp_s = t1 + t2;
        float resp_c = t3 - t4;
        float v = resp_s * resp_s + resp_c * resp_c;
        op[t * NF] = logf(sqrtf(v) + 1e-5f);

        int tn = t + 8;
        int i = tn & 15;
        rs[i] = (tn < T_LEN) ? gs[tn * NF] : 0.f;
        rc[i] = (tn < T_LEN) ? gc[tn * NF] : 0.f;
    }
}

extern "C" void kernel_launch(void* const* d_in, const int* in_sizes, int n_in,
                              void* d_out, int out_size) {
    const float* x       = (const float*)d_in[0];
    const float* w_s_sin = (const float*)d_in[1];
    const float* w_s_cos = (const float*)d_in[2];
    const float* w_t_sin = (const float*)d_in[3];
    const float* w_t_cos = (const float*)d_in[4];
    float* out = (float*)d_out;

    __half *dx, *dws, *dwc;
    cudaGetSymbolAddress((void**)&dx,  x_h);
    cudaGetSymbolAddress((void**)&dws, ws_h);
    cudaGetSymbolAddress((void**)&dwc, wc_h);

    const int nx4 = BT * HWDIM / 4;
    const int nw4 = NF * HWDIM / 4;
    f2h_kernel<<<(nx4 + 255) / 256, 256>>>(x, dx, nx4);
    f2h_kernel<<<(nw4 + 255) / 256, 256>>>(w_s_sin, dws, nw4);
    f2h_kernel<<<(nw4 + 255) / 256, 256>>>(w_s_cos, dwc, nw4);

    static bool attr_set = false;
    if (!attr_set) {
        cudaFuncSetAttribute(spatial_gemm_fp16,
                             cudaFuncAttributeMaxDynamicSharedMemorySize, SMEM_DYN);
        attr_set = true;
    }
    dim3 g1(NF / BNF, BT / BM);        // (20, 15) = 300 CTAs
    spatial_gemm_fp16<<<g1, 256, SMEM_DYN>>>(0);

    dim3 g2(NF / 256, BATCH, T_LEN / 48);   // (10, 8, 5)
    temporal_kernel<<<g2, 256>>>(w_t_sin, w_t_cos, out);
}

// round 4
// speedup vs baseline: 2.0805x; 1.2148x over previous
#include <cuda_runtime.h>
#include <cuda_fp16.h>
#include <cstdint>

#define NF      2560
#define TW      16
#define HWDIM   9216
#define BT      1920
#define T_LEN   240
#define BATCH   8

#define BM      128     // bt rows per CTA (M)
#define BNF     128     // filters per CTA (N)
#define KC      32      // K elements per stage
#define NCHUNK  288     // 9216/32
#define PADROWB 80      // bytes per smem row (32 halves = 64B + 16B pad)
#define OFF_A   0
#define OFF_B   (128 * PADROWB)          // 10240
#define STG_BYTES (256 * PADROWB)        // 20480
#define SMEM_DYN  (3 * STG_BYTES)        // 61440

// fp16 copies of inputs (filled by convert kernel)
__device__ __half x_h[BT * HWDIM];
__device__ __half ws_h[NF * HWDIM];
__device__ __half wc_h[NF * HWDIM];
// intermediate g_sin / g_cos, layout [bt][f]
__device__ float g_buf0[BT * NF];
__device__ float g_buf1[BT * NF];

// ---------------------------------------------------------------------------
__device__ __forceinline__ unsigned smem_u32(const void* p) {
    return (unsigned)__cvta_generic_to_shared(p);
}
__device__ __forceinline__ void cp_async16(unsigned saddr, const void* gaddr) {
    asm volatile("cp.async.cg.shared.global [%0], [%1], 16;\n" :: "r"(saddr), "l"(gaddr));
}
__device__ __forceinline__ void ldsm_x4(uint32_t* r, unsigned addr) {
    asm volatile("ldmatrix.sync.aligned.m8n8.x4.shared.b16 {%0,%1,%2,%3}, [%4];"
                 : "=r"(r[0]), "=r"(r[1]), "=r"(r[2]), "=r"(r[3]) : "r"(addr));
}
__device__ __forceinline__ void mma_fp16(float* c, const uint32_t* a, const uint32_t* b) {
    asm volatile(
        "mma.sync.aligned.m16n8k16.row.col.f32.f16.f16.f32 "
        "{%0,%1,%2,%3}, {%4,%5,%6,%7}, {%8,%9}, {%0,%1,%2,%3};\n"
        : "+f"(c[0]), "+f"(c[1]), "+f"(c[2]), "+f"(c[3])
        : "r"(a[0]), "r"(a[1]), "r"(a[2]), "r"(a[3]), "r"(b[0]), "r"(b[1]));
}

// ---------------------------------------------------------------------------
// Kernel 0: fp32 -> fp16 conversion (vectorized)
// ---------------------------------------------------------------------------
__global__ void __launch_bounds__(256)
f2h_kernel(const float* __restrict__ src, __half* __restrict__ dst, int n4) {
    int i = blockIdx.x * 256 + threadIdx.x;
    if (i < n4) {
        float4 v = reinterpret_cast<const float4*>(src)[i];
        reinterpret_cast<__half2*>(dst)[2 * i]     = __floats2half2_rn(v.x, v.y);
        reinterpret_cast<__half2*>(dst)[2 * i + 1] = __floats2half2_rn(v.z, v.w);
    }
}

// ---------------------------------------------------------------------------
// Kernel 1: spatial GEMM, fp16 mma.sync, 3-stage cp.async, 2 CTAs/SM.
//   g[m, f] = sum_k x[m,k] * w[f,k]
// Block tile 128(m) x 128(f), 256 threads, warp tile 64m x 32f.
// blockIdx.z: 0 -> ws_h -> g_buf0, 1 -> wc_h -> g_buf1.
// ---------------------------------------------------------------------------
__global__ void __launch_bounds__(256, 2)
spatial_gemm_fp16(int dummy) {
    extern __shared__ __align__(1024) char smem[];
    const unsigned smem_base = smem_u32(smem);
    const int tid = threadIdx.x;
    const int n0 = blockIdx.x * BNF;   // filter base
    const int m0 = blockIdx.y * BM;    // bt base
    const __half* wmat = blockIdx.z ? wc_h : ws_h;
    float* gout = blockIdx.z ? g_buf1 : g_buf0;

    const int lane = tid & 31;
    const int warp = tid >> 5;
    const int wm = (warp & 1) * 64;
    const int wn = (warp >> 1) * 32;

    float acc[4][4][4];
    #pragma unroll
    for (int i = 0; i < 4; i++)
        #pragma unroll
        for (int j = 0; j < 4; j++)
            #pragma unroll
            for (int k = 0; k < 4; k++) acc[i][j][k] = 0.f;

    // loader: row = tid>>2 (0..63, +64), seg = tid&3 (16B each); 2 xfers/array
    const int lrow = tid >> 2;
    const int seg = tid & 3;
    const __half* ga = x_h  + (size_t)(m0 + lrow) * HWDIM + seg * 8;
    const __half* gb = wmat + (size_t)(n0 + lrow) * HWDIM + seg * 8;
    const unsigned lsm = smem_base + lrow * PADROWB + seg * 16;

    auto load_stage = [&](int kt, int slot) {
        const unsigned sb = lsm + slot * STG_BYTES;
        const __half* pa = ga + kt * KC;
        const __half* pb = gb + kt * KC;
        #pragma unroll
        for (int i = 0; i < 2; i++) {
            cp_async16(sb + OFF_A + i * 64 * PADROWB, pa + (size_t)i * 64 * HWDIM);
            cp_async16(sb + OFF_B + i * 64 * PADROWB, pb + (size_t)i * 64 * HWDIM);
        }
        asm volatile("cp.async.commit_group;\n");
    };

    // ldmatrix per-lane byte offsets within a stage
    const int mrow = wm + (lane & 7) + 8 * ((lane >> 3) & 1);
    const int akb  = (lane >> 4) * 16;
    unsigned aoff[4];
    #pragma unroll
    for (int mt = 0; mt < 4; mt++) aoff[mt] = (mrow + mt * 16) * PADROWB + akb;

    const int nrow = wn + (lane & 7) + 8 * (lane >> 4);
    const int bkb  = ((lane >> 3) & 1) * 16;
    unsigned boff[2];
    #pragma unroll
    for (int p = 0; p < 2; p++) boff[p] = (nrow + p * 16) * PADROWB + bkb;

    // prologue
    load_stage(0, 0);
    load_stage(1, 1);

    for (int kt = 0; kt < NCHUNK; kt++) {
        if (kt < NCHUNK - 1) asm volatile("cp.async.wait_group 1;\n");
        else                 asm volatile("cp.async.wait_group 0;\n");
        __syncthreads();
        if (kt + 2 < NCHUNK) load_stage(kt + 2, (kt + 2) % 3);

        const unsigned sb = smem_base + (kt % 3) * STG_BYTES;
        #pragma unroll
        for (int kk = 0; kk < 2; kk++) {
            const unsigned kb = kk * 32;
            uint32_t a[4][4], b[2][4];
            #pragma unroll
            for (int mt = 0; mt < 4; mt++) ldsm_x4(a[mt], sb + OFF_A + aoff[mt] + kb);
            #pragma unroll
            for (int p = 0; p < 2; p++) ldsm_x4(b[p], sb + OFF_B + boff[p] + kb);
            #pragma unroll
            for (int mt = 0; mt < 4; mt++)
                #pragma unroll
                for (int nt = 0; nt < 4; nt++)
                    mma_fp16(acc[mt][nt], a[mt], &b[nt >> 1][(nt & 1) * 2]);
        }
        __syncthreads();
    }

    // epilogue
    #pragma unroll
    for (int mt = 0; mt < 4; mt++) {
        #pragma unroll
        for (int nt = 0; nt < 4; nt++) {
            int m = m0 + wm + mt * 16 + (lane >> 2);
            int n = n0 + wn + nt * 8 + (lane & 3) * 2;
            *reinterpret_cast<float2*>(&gout[(size_t)m * NF + n]) =
                make_float2(acc[mt][nt][0], acc[mt][nt][1]);
            *reinterpret_cast<float2*>(&gout[(size_t)(m + 8) * NF + n]) =
                make_float2(acc[mt][nt][2], acc[mt][nt][3]);
        }
    }
}

// ---------------------------------------------------------------------------
// Kernel 2: depthwise temporal convs + energy. Ring-buffer sliding window,
// T split into 5 chunks of 48.
// ---------------------------------------------------------------------------
__global__ void __launch_bounds__(256)
temporal_kernel(const float* __restrict__ wt_sin_g,
                const float* __restrict__ wt_cos_g,
                float* __restrict__ out) {
    const int f = blockIdx.x * 256 + threadIdx.x;
    const int b = blockIdx.y;
    const int t0 = blockIdx.z * 48;

    float wts[TW], wtc[TW];
    #pragma unroll
    for (int j = 0; j < TW; j++) {
        wts[j] = wt_sin_g[f * TW + j];
        wtc[j] = wt_cos_g[f * TW + j];
    }

    const float* gs = g_buf0 + (size_t)b * T_LEN * NF + f;
    const float* gc = g_buf1 + (size_t)b * T_LEN * NF + f;
    float* op = out + (size_t)b * T_LEN * NF + f;

    float rs[TW], rc[TW];
    #pragma unroll
    for (int j = 0; j < TW; j++) {
        int t = t0 - 8 + j;
        int i = t & 15;
        rs[i] = (t >= 0) ? gs[t * NF] : 0.f;
        rc[i] = (t >= 0) ? gc[t * NF] : 0.f;
    }

    #pragma unroll 16
    for (int tt = 0; tt < 48; tt++) {
        const int t = t0 + tt;
        float t1 = 0.f, t2 = 0.f, t3 = 0.f, t4 = 0.f;
        #pragma unroll
        for (int j = 0; j < TW; j++) {
            int i = (tt - 8 + j) & 15;
            t1 += rs[i] * wtc[j];
            t2 += rc[i] * wts[j];
            t3 += rc[i] * wtc[j];
            t4 += rs[i] * wts[j];
        }
        float resp_s = t1 + t2;
        float resp_c = t3 - t4;
        float v = resp_s * resp_s + resp_c * resp_c;
        op[t * NF] = logf(sqrtf(v) + 1e-5f);

        int tn = t + 8;
        int i = tn & 15;
        rs[i] = (tn < T_LEN) ? gs[tn * NF] : 0.f;
        rc[i] = (tn < T_LEN) ? gc[tn * NF] : 0.f;
    }
}

extern "C" void kernel_launch(void* const* d_in, const int* in_sizes, int n_in,
                              void* d_out, int out_size) {
    const float* x       = (const float*)d_in[0];
    const float* w_s_sin = (const float*)d_in[1];
    const float* w_s_cos = (const float*)d_in[2];
    const float* w_t_sin = (const float*)d_in[3];
    const float* w_t_cos = (const float*)d_in[4];
    float* out = (float*)d_out;

    __half *dx, *dws, *dwc;
    cudaGetSymbolAddress((void**)&dx,  x_h);
    cudaGetSymbolAddress((void**)&dws, ws_h);
    cudaGetSymbolAddress((void**)&dwc, wc_h);

    const int nx4 = BT * HWDIM / 4;
    const int nw4 = NF * HWDIM / 4;
    f2h_kernel<<<(nx4 + 255) / 256, 256>>>(x, dx, nx4);
    f2h_kernel<<<(nw4 + 255) / 256, 256>>>(w_s_sin, dws, nw4);
    f2h_kernel<<<(nw4 + 255) / 256, 256>>>(w_s_cos, dwc, nw4);

    cudaFuncSetAttribute(spatial_gemm_fp16,
                         cudaFuncAttributeMaxDynamicSharedMemorySize, SMEM_DYN);

    dim3 g1(NF / BNF, BT / BM, 2);     // (20, 15, 2) = 600 CTAs, 2/SM
    spatial_gemm_fp16<<<g1, 256, SMEM_DYN>>>(0);

    dim3 g2(NF / 256, BATCH, T_LEN / 48);   // (10, 8, 5)
    temporal_kernel<<<g2, 256>>>(w_t_sin, w_t_cos, out);
}